// round 2
// baseline (speedup 1.0000x reference)
#include <cuda_runtime.h>
#include <cstdint>
#include <math.h>

// ---------------- Problem constants ----------------
#define D_MODEL   1024
#define HEADDIM   64
#define D_STATE   128
#define D_CONVW   4
#define D_INNER   2048
#define NHEADS    32
#define CONV_DIM  2304           // D_INNER + 2*D_STATE
#define D_IN_PROJ 4384           // 2*D_INNER + 2*D_STATE + NHEADS
#define BATCH     4
#define SEQ       2048
#define ROWS      (BATCH*SEQ)    // 8192
#define EPSV      1e-5f

typedef unsigned long long ull;

// ---------------- Scratch (static device memory; no allocations) ----------------
__device__ float g_zxb[(size_t)ROWS * D_IN_PROJ];   // in-proj output  (~143 MB)
__device__ float g_xbc[(size_t)ROWS * CONV_DIM];    // conv+silu output (~75 MB)
__device__ float g_dt [BATCH*NHEADS*SEQ];           // softplus(dt)  [b][h][l]
__device__ float g_dA [BATCH*NHEADS*SEQ];           // exp(A*dt)     [b][h][l]
__device__ float g_yb [(size_t)ROWS * D_INNER];     // scan output + D*x
__device__ float g_yn [(size_t)ROWS * D_INNER];     // gated + rmsnormed

// ---------------- f32x2 packed helpers (sm_100+) ----------------
__device__ __forceinline__ ull pack2(float lo, float hi) {
    ull r; asm("mov.b64 %0, {%1,%2};" : "=l"(r) : "f"(lo), "f"(hi)); return r;
}
__device__ __forceinline__ void unpack2(ull v, float& lo, float& hi) {
    asm("mov.b64 {%0,%1}, %2;" : "=f"(lo), "=f"(hi) : "l"(v));
}
// d = a*b + d   (elementwise on packed f32x2)
__device__ __forceinline__ void fma2(ull& d, ull a, ull b) {
    asm("fma.rn.f32x2 %0, %1, %2, %0;" : "+l"(d) : "l"(a), "l"(b));
}
__device__ __forceinline__ ull mul2(ull a, ull b) {
    ull r; asm("mul.rn.f32x2 %0, %1, %2;" : "=l"(r) : "l"(a), "l"(b)); return r;
}

// ---------------- cp.async helpers ----------------
__device__ __forceinline__ void cp_async16(void* smem, const void* gmem) {
    unsigned s = (unsigned)__cvta_generic_to_shared(smem);
    asm volatile("cp.async.ca.shared.global [%0], [%1], 16;" :: "r"(s), "l"(gmem));
}
__device__ __forceinline__ void cp_commit() { asm volatile("cp.async.commit_group;"); }
template<int N> __device__ __forceinline__ void cp_wait() {
    asm volatile("cp.async.wait_group %0;" :: "n"(N));
}

// =====================================================================
// GEMM (NT): C[M,N] = A[M,K] * B[N,K]^T    (both row-major, K contiguous)
// 128x128 tile, BK=16, 256 threads, 8x8 per thread.
// Accumulators are packed f32x2 over column pairs -> FFMA2 full-rate fp32.
// =====================================================================
__global__ __launch_bounds__(256) void gemm_nt(const float* __restrict__ A,
                                               const float* __restrict__ B,
                                               float* __restrict__ C,
                                               int M, int N, int K)
{
    __shared__ float As[16][128];
    __shared__ float Bs[16][128];
    const int tid = threadIdx.x;
    const int tx  = tid & 15;
    const int ty  = tid >> 4;
    const int m0  = blockIdx.x * 128;
    const int n0  = blockIdx.y * 128;

    ull acc[8][4];
#pragma unroll
    for (int r = 0; r < 8; r++)
#pragma unroll
        for (int c = 0; c < 4; c++) acc[r][c] = 0ull;

    const int i0 = tid * 2, i1 = tid * 2 + 1;
    const int ra0 = i0 >> 2, ka0 = (i0 & 3) * 4;
    const int ra1 = i1 >> 2, ka1 = (i1 & 3) * 4;

    float4 av0, av1, bv0, bv1;
    // prologue: load k-tile 0 into registers
    av0 = *(const float4*)(A + (size_t)(m0 + ra0) * K + ka0);
    av1 = *(const float4*)(A + (size_t)(m0 + ra1) * K + ka1);
    bv0 = (n0 + ra0 < N) ? *(const float4*)(B + (size_t)(n0 + ra0) * K + ka0)
                         : make_float4(0.f,0.f,0.f,0.f);
    bv1 = (n0 + ra1 < N) ? *(const float4*)(B + (size_t)(n0 + ra1) * K + ka1)
                         : make_float4(0.f,0.f,0.f,0.f);

    for (int k0 = 0; k0 < K; k0 += 16) {
        // stage current tile to smem
        As[ka0+0][ra0] = av0.x; As[ka0+1][ra0] = av0.y; As[ka0+2][ra0] = av0.z; As[ka0+3][ra0] = av0.w;
        As[ka1+0][ra1] = av1.x; As[ka1+1][ra1] = av1.y; As[ka1+2][ra1] = av1.z; As[ka1+3][ra1] = av1.w;
        Bs[ka0+0][ra0] = bv0.x; Bs[ka0+1][ra0] = bv0.y; Bs[ka0+2][ra0] = bv0.z; Bs[ka0+3][ra0] = bv0.w;
        Bs[ka1+0][ra1] = bv1.x; Bs[ka1+1][ra1] = bv1.y; Bs[ka1+2][ra1] = bv1.z; Bs[ka1+3][ra1] = bv1.w;
        __syncthreads();

        // prefetch next tile (overlaps with compute below)
        if (k0 + 16 < K) {
            const int kn = k0 + 16;
            av0 = *(const float4*)(A + (size_t)(m0 + ra0) * K + kn + ka0);
            av1 = *(const float4*)(A + (size_t)(m0 + ra1) * K + kn + ka1);
            bv0 = (n0 + ra0 < N) ? *(const float4*)(B + (size_t)(n0 + ra0) * K + kn + ka0)
                                 : make_float4(0.f,0.f,0.f,0.f);
            bv1 = (n0 + ra1 < N) ? *(const float4*)(B + (size_t)(n0 + ra1) * K + kn + ka1)
                                 : make_float4(0.f,0.f,0.f,0.f);
        }

#pragma unroll
        for (int kk = 0; kk < 16; kk++) {
            float a[8];
#pragma unroll
            for (int j = 0; j < 4; j++) {
                a[j]     = As[kk][ty*4 + j];
                a[j + 4] = As[kk][64 + ty*4 + j];
            }
            ull bp[4];
            bp[0] = *(const ull*)&Bs[kk][tx*4];
            bp[1] = *(const ull*)&Bs[kk][tx*4 + 2];
            bp[2] = *(const ull*)&Bs[kk][64 + tx*4];
            bp[3] = *(const ull*)&Bs[kk][64 + tx*4 + 2];
#pragma unroll
            for (int r = 0; r < 8; r++) {
                ull aa = pack2(a[r], a[r]);
#pragma unroll
                for (int c = 0; c < 4; c++) fma2(acc[r][c], aa, bp[c]);
            }
        }
        __syncthreads();
    }

    // epilogue: each acc is a float2 over adjacent columns
#pragma unroll
    for (int r = 0; r < 8; r++) {
        const int row = m0 + ((r < 4) ? (ty*4 + r) : (64 + ty*4 + r - 4));
#pragma unroll
        for (int c = 0; c < 4; c++) {
            const int col = n0 + ((c < 2) ? (tx*4 + c*2) : (64 + tx*4 + (c-2)*2));
            if (col < N) {
                float lo, hi; unpack2(acc[r][c], lo, hi);
                *(float2*)(C + (size_t)row * N + col) = make_float2(lo, hi);
            }
        }
    }
}

// =====================================================================
// Depthwise causal conv (width 4) + SiLU over xBC slice of zxbcdt
// grid: (CONV_DIM/256, SEQ/128, BATCH)
// =====================================================================
__global__ __launch_bounds__(256) void conv_silu_kernel(const float* __restrict__ conv_w,
                                                        const float* __restrict__ conv_b)
{
    const int c  = blockIdx.x * 256 + threadIdx.x;
    const int l0 = blockIdx.y * 128;
    const int b  = blockIdx.z;

    const float w0 = conv_w[c*4+0], w1 = conv_w[c*4+1],
                w2 = conv_w[c*4+2], w3 = conv_w[c*4+3];
    const float bias = conv_b[c];

    const float* src = g_zxb + (size_t)(b*SEQ) * D_IN_PROJ + D_INNER + c;
    float*       dst = g_xbc + (size_t)(b*SEQ) * CONV_DIM + c;

    float xm3 = (l0-3 >= 0) ? src[(size_t)(l0-3) * D_IN_PROJ] : 0.f;
    float xm2 = (l0-2 >= 0) ? src[(size_t)(l0-2) * D_IN_PROJ] : 0.f;
    float xm1 = (l0-1 >= 0) ? src[(size_t)(l0-1) * D_IN_PROJ] : 0.f;

    for (int l = l0; l < l0 + 128; l++) {
        const float xc = src[(size_t)l * D_IN_PROJ];
        float v = bias + w0*xm3 + w1*xm2 + w2*xm1 + w3*xc;
        v = v / (1.f + expf(-v));                 // SiLU
        dst[(size_t)l * CONV_DIM] = v;
        xm3 = xm2; xm2 = xm1; xm1 = xc;
    }
}

// =====================================================================
// dt = softplus(raw + dt_bias); dA = exp(-exp(A_log)*dt)   layout [b][h][l]
// =====================================================================
__global__ __launch_bounds__(256) void dt_kernel(const float* __restrict__ dt_bias,
                                                 const float* __restrict__ A_log)
{
    const int idx = blockIdx.x * 256 + threadIdx.x;       // 262144 total
    if (idx >= BATCH*NHEADS*SEQ) return;
    const int l = idx & (SEQ-1);
    const int h = (idx >> 11) & (NHEADS-1);
    const int b = idx >> 16;
    const float raw = g_zxb[(size_t)(b*SEQ + l) * D_IN_PROJ + (D_IN_PROJ - NHEADS) + h]
                      + dt_bias[h];
    const float sp = (raw > 20.f) ? raw : log1pf(expf(raw));
    const float Ah = -expf(A_log[h]);
    g_dt[idx] = sp;
    g_dA[idx] = expf(Ah * sp);
}

// =====================================================================
// Selective scan: one CTA per (b, head). State h[64][128] distributed:
// thread (p = tid>>2, q = tid&3) owns 32 states as 16 packed f32x2.
// 8-step cp.async double-buffered staging of B/C/x.
// =====================================================================
__global__ __launch_bounds__(256) void scan_kernel(const float* __restrict__ Dvec)
{
    const int bh  = blockIdx.x;            // 0..127
    const int b   = bh >> 5;
    const int hh  = bh & (NHEADS-1);
    const int tid = threadIdx.x;
    const int p   = tid >> 2;              // 0..63
    const int q   = tid & 3;               // 0..3

    __shared__ __align__(16) float sB[2][8][D_STATE];
    __shared__ __align__(16) float sC[2][8][D_STATE];
    __shared__ __align__(16) float sX[2][8][HEADDIM];
    __shared__ float sDt[SEQ];
    __shared__ float sDA[SEQ];

    const float* dtp = g_dt + (size_t)bh * SEQ;
    const float* dap = g_dA + (size_t)bh * SEQ;
    for (int i = tid; i < SEQ; i += 256) { sDt[i] = dtp[i]; sDA[i] = dap[i]; }

    const float Dv = Dvec[hh];

    ull h2[16];
#pragma unroll
    for (int i = 0; i < 16; i++) h2[i] = 0ull;

    auto preload = [&](int blk, int buf) {
        const int t0 = blk * 8;
        {   // B and C: 8 steps x 128 floats = 256 float4 each -> 1 per thread
            const int s = tid >> 5, seg = tid & 31;
            const float* rowp = g_xbc + (size_t)(b*SEQ + t0 + s) * CONV_DIM;
            cp_async16(&sB[buf][s][seg*4], rowp + D_INNER + seg*4);
            cp_async16(&sC[buf][s][seg*4], rowp + D_INNER + D_STATE + seg*4);
        }
        if (tid < 128) {  // x: 8 steps x 64 floats = 128 float4
            const int s = tid >> 4, seg = tid & 15;
            const float* rowp = g_xbc + (size_t)(b*SEQ + t0 + s) * CONV_DIM;
            cp_async16(&sX[buf][s][seg*4], rowp + hh*HEADDIM + seg*4);
        }
        cp_commit();
    };

    const int NBLK = SEQ / 8;
    int buf = 0;
    preload(0, 0);

    for (int blk = 0; blk < NBLK; blk++) {
        if (blk + 1 < NBLK) { preload(blk + 1, buf ^ 1); cp_wait<1>(); }
        else                { cp_wait<0>(); }
        __syncthreads();

#pragma unroll
        for (int s = 0; s < 8; s++) {
            const int t = blk*8 + s;
            const float dtv = sDt[t];
            const float dav = sDA[t];
            const float xv  = sX[buf][s][p];
            const float coef = dtv * xv;
            const ull dA2 = pack2(dav, dav);
            const ull cf2 = pack2(coef, coef);
            const ull* Bp = (const ull*)&sB[buf][s][q*32];
            const ull* Cp = (const ull*)&sC[buf][s][q*32];
            ull yacc = 0ull;
#pragma unroll
            for (int i = 0; i < 16; i++) {
                ull t2 = mul2(cf2, Bp[i]);    // dt * x * B
                fma2(t2, h2[i], dA2);         // += h * dA
                h2[i] = t2;
                fma2(yacc, t2, Cp[i]);        // y += h * C
            }
            float ylo, yhi; unpack2(yacc, ylo, yhi);
            float yv = ylo + yhi;
            yv += __shfl_xor_sync(0xffffffffu, yv, 1);
            yv += __shfl_xor_sync(0xffffffffu, yv, 2);
            if (q == 0) {
                g_yb[((size_t)(b*SEQ + t) * NHEADS + hh) * HEADDIM + p] = yv + Dv * xv;
            }
        }
        __syncthreads();
        buf ^= 1;
    }
}

// =====================================================================
// y = yb * silu(z); y *= rsqrt(mean(y^2)+eps) * norm_w    one CTA per row
// =====================================================================
__global__ __launch_bounds__(256) void gate_norm_kernel(const float* __restrict__ norm_w)
{
    const int row = blockIdx.x;
    const int tid = threadIdx.x;
    const float* yb = g_yb + (size_t)row * D_INNER;
    const float* zr = g_zxb + (size_t)row * D_IN_PROJ;   // z = first 2048 cols

    float v[8];
    float ss = 0.f;
#pragma unroll
    for (int j = 0; j < 8; j++) {
        const int idx = tid + j*256;
        const float z = zr[idx];
        const float sg = z / (1.f + expf(-z));
        const float val = yb[idx] * sg;
        v[j] = val;
        ss += val * val;
    }
#pragma unroll
    for (int o = 16; o > 0; o >>= 1) ss += __shfl_xor_sync(0xffffffffu, ss, o);

    __shared__ float red[8];
    __shared__ float sscale;
    if ((tid & 31) == 0) red[tid >> 5] = ss;
    __syncthreads();
    if (tid == 0) {
        float tot = 0.f;
#pragma unroll
        for (int i = 0; i < 8; i++) tot += red[i];
        sscale = rsqrtf(tot / (float)D_INNER + EPSV);
    }
    __syncthreads();
    const float scale = sscale;

    float* out = g_yn + (size_t)row * D_INNER;
#pragma unroll
    for (int j = 0; j < 8; j++) {
        const int idx = tid + j*256;
        out[idx] = v[j] * scale * norm_w[idx];
    }
}

// =====================================================================
// Launch
// inputs: 0 query, 1 key, 2 value, 3 in_proj_w, 4 conv_w, 5 conv_b,
//         6 dt_bias, 7 A_log, 8 D, 9 norm_w, 10 out_proj_w
// =====================================================================
extern "C" void kernel_launch(void* const* d_in, const int* in_sizes, int n_in,
                              void* d_out, int out_size)
{
    const float* q          = (const float*)d_in[0];
    const float* in_proj_w  = (const float*)d_in[3];
    const float* conv_w     = (const float*)d_in[4];
    const float* conv_b     = (const float*)d_in[5];
    const float* dt_bias    = (const float*)d_in[6];
    const float* A_log      = (const float*)d_in[7];
    const float* Dvec       = (const float*)d_in[8];
    const float* norm_w     = (const float*)d_in[9];
    const float* out_proj_w = (const float*)d_in[10];
    float* out              = (float*)d_out;

    float* zxb; cudaGetSymbolAddress((void**)&zxb, g_zxb);
    float* yn;  cudaGetSymbolAddress((void**)&yn,  g_yn);

    // 1) zxbcdt = q @ in_proj_w^T : [8192,1024] x [4384,1024]^T
    gemm_nt<<<dim3(ROWS/128, (D_IN_PROJ + 127)/128), 256>>>(q, in_proj_w, zxb,
                                                            ROWS, D_IN_PROJ, D_MODEL);
    // 2) causal conv4 + SiLU on xBC
    conv_silu_kernel<<<dim3(CONV_DIM/256, SEQ/128, BATCH), 256>>>(conv_w, conv_b);
    // 3) dt / dA
    dt_kernel<<<(BATCH*NHEADS*SEQ + 255)/256, 256>>>(dt_bias, A_log);
    // 4) selective scan
    scan_kernel<<<BATCH*NHEADS, 256>>>(Dvec);
    // 5) gate + RMSNorm
    gate_norm_kernel<<<ROWS, 256>>>(norm_w);
    // 6) out = yn @ out_proj_w^T : [8192,2048] x [1024,2048]^T
    gemm_nt<<<dim3(ROWS/128, D_MODEL/128), 256>>>(yn, out_proj_w, out,
                                                  ROWS, D_MODEL, D_INNER);
}

// round 6
// speedup vs baseline: 1.4103x; 1.4103x over previous
#include <cuda_runtime.h>
#include <cuda_bf16.h>
#include <cstdint>
#include <math.h>

// ---------------- Problem constants ----------------
#define D_MODEL   1024
#define HEADDIM   64
#define D_STATE   128
#define D_INNER   2048
#define NHEADS    32
#define CONV_DIM  2304           // D_INNER + 2*D_STATE
#define D_IN_PROJ 4384           // 2*D_INNER + 2*D_STATE + NHEADS
#define BATCH     4
#define SEQ       2048
#define ROWS      (BATCH*SEQ)    // 8192
#define EPSV      1e-5f

typedef unsigned long long ull;

// ---------------- Scratch (static device memory; no allocations) ----------------
__device__ float g_zxb[(size_t)ROWS * D_IN_PROJ];   // in-proj output
__device__ float g_xbc[(size_t)ROWS * CONV_DIM];    // conv+silu output
__device__ float g_dt [BATCH*NHEADS*SEQ];
__device__ float g_dA [BATCH*NHEADS*SEQ];
__device__ float g_yb [(size_t)ROWS * D_INNER];     // scan output + D*x

// bf16 split operands for tensor-core GEMMs
__device__ __nv_bfloat16 g_qh [(size_t)ROWS * D_MODEL];
__device__ __nv_bfloat16 g_ql [(size_t)ROWS * D_MODEL];
__device__ __nv_bfloat16 g_w1h[(size_t)D_IN_PROJ * D_MODEL];
__device__ __nv_bfloat16 g_w1l[(size_t)D_IN_PROJ * D_MODEL];
__device__ __nv_bfloat16 g_ynh[(size_t)ROWS * D_INNER];
__device__ __nv_bfloat16 g_ynl[(size_t)ROWS * D_INNER];
__device__ __nv_bfloat16 g_w2h[(size_t)D_MODEL * D_INNER];
__device__ __nv_bfloat16 g_w2l[(size_t)D_MODEL * D_INNER];

// ---------------- f32x2 packed helpers (sm_100+) ----------------
__device__ __forceinline__ ull pack2(float lo, float hi) {
    ull r; asm("mov.b64 %0, {%1,%2};" : "=l"(r) : "f"(lo), "f"(hi)); return r;
}
__device__ __forceinline__ void unpack2(ull v, float& lo, float& hi) {
    asm("mov.b64 {%0,%1}, %2;" : "=f"(lo), "=f"(hi) : "l"(v));
}
__device__ __forceinline__ void fma2(ull& d, ull a, ull b) {
    asm("fma.rn.f32x2 %0, %1, %2, %0;" : "+l"(d) : "l"(a), "l"(b));
}
__device__ __forceinline__ ull mul2(ull a, ull b) {
    ull r; asm("mul.rn.f32x2 %0, %1, %2;" : "=l"(r) : "l"(a), "l"(b)); return r;
}

// ---------------- cp.async helpers ----------------
__device__ __forceinline__ void cp16(unsigned s, const void* g) {
    asm volatile("cp.async.ca.shared.global [%0], [%1], 16;" :: "r"(s), "l"(g));
}
__device__ __forceinline__ void cp16z(unsigned s, const void* g, unsigned sz) {
    asm volatile("cp.async.ca.shared.global [%0], [%1], 16, %2;" :: "r"(s), "l"(g), "r"(sz));
}
__device__ __forceinline__ void cp_commit() { asm volatile("cp.async.commit_group;"); }
template<int N> __device__ __forceinline__ void cp_wait() {
    asm volatile("cp.async.wait_group %0;" :: "n"(N));
}
__device__ __forceinline__ unsigned smem_u32(const void* p) {
    return (unsigned)__cvta_generic_to_shared(p);
}

// ---------------- mma.sync + ldmatrix (arch-portable, works on base sm_103) ----
#define LDSM4(r, addr) \
    asm volatile("ldmatrix.sync.aligned.m8n8.x4.shared.b16 {%0,%1,%2,%3}, [%4];" \
        : "=r"((r)[0]), "=r"((r)[1]), "=r"((r)[2]), "=r"((r)[3]) : "r"(addr))

#define MMA16816(d, a, b) \
    asm volatile("mma.sync.aligned.m16n8k16.row.col.f32.bf16.bf16.f32 " \
        "{%0,%1,%2,%3}, {%4,%5,%6,%7}, {%8,%9}, {%0,%1,%2,%3};" \
        : "+f"((d)[0]), "+f"((d)[1]), "+f"((d)[2]), "+f"((d)[3]) \
        : "r"((a)[0]), "r"((a)[1]), "r"((a)[2]), "r"((a)[3]), \
          "r"((b)[0]), "r"((b)[1]))

// =====================================================================
// Split-bf16 HMMA GEMM (NT): C[M,N] = A[M,K] * B[N,K]^T
// C = Ah*Bh + Al*Bh + Ah*Bl (fp32 accum) -> ~1e-5 rel err
// CTA tile 128(M) x 256(N), BK=64, 8 warps (2x4) of 64x64 warp tiles.
// SMEM stage (96KB, double buffered): Ah@0 16K | Al@16K | Bh@32K 32K | Bl@64K
// 128B rows of 64 bf16, 16B-chunk XOR swizzle: phys_c = c ^ (row&7).
// =====================================================================
#define GEMM_STG   98304
#define GEMM_SMEM  (2*GEMM_STG)

__global__ void __launch_bounds__(256, 1)
gemm_mma(const __nv_bfloat16* __restrict__ A_h, const __nv_bfloat16* __restrict__ A_l,
         const __nv_bfloat16* __restrict__ B_h, const __nv_bfloat16* __restrict__ B_l,
         float* __restrict__ C, int M, int N, int K)
{
    extern __shared__ __align__(1024) char sm[];
    const unsigned base = smem_u32(sm);
    const int tid  = threadIdx.x;
    const int lane = tid & 31;
    const int wid  = tid >> 5;
    const int wm   = wid >> 2;          // 0..1  (M half)
    const int wn   = wid & 3;           // 0..3  (N quarter)
    const int m0   = blockIdx.y * 128;
    const int n0   = blockIdx.x * 256;

    float acc[4][8][4];
#pragma unroll
    for (int t = 0; t < 4; t++)
#pragma unroll
        for (int u = 0; u < 8; u++)
#pragma unroll
            for (int v = 0; v < 4; v++) acc[t][u][v] = 0.f;

    auto load_stage = [&](int s, unsigned stg) {
        const int k0 = s * 64;
        // A hi/lo: 128 rows x 8 chunks of 16B -> 1024 chunks, 4/thread/matrix
#pragma unroll
        for (int i = 0; i < 4; i++) {
            const int ch = tid + i * 256;
            const int row = ch >> 3, c = ch & 7;
            const unsigned off = (unsigned)(row * 128) + ((unsigned)(c ^ (row & 7)) << 4);
            const size_t g = (size_t)(m0 + row) * K + k0 + c * 8;
            cp16(stg + off,         A_h + g);
            cp16(stg + 16384 + off, A_l + g);
        }
        // B hi/lo: 256 rows x 8 chunks -> 2048 chunks, 8/thread/matrix
#pragma unroll
        for (int i = 0; i < 8; i++) {
            const int ch = tid + i * 256;
            const int row = ch >> 3, c = ch & 7;
            const unsigned off = (unsigned)(row * 128) + ((unsigned)(c ^ (row & 7)) << 4);
            const int gr = n0 + row;
            const unsigned sz = (gr < N) ? 16u : 0u;
            const int grc = (gr < N) ? gr : 0;
            const size_t g = (size_t)grc * K + k0 + c * 8;
            cp16z(stg + 32768 + off, B_h + g, sz);
            cp16z(stg + 65536 + off, B_l + g, sz);
        }
        cp_commit();
    };

    const int S = K / 64;
    load_stage(0, base);

    for (int s = 0; s < S; s++) {
        const unsigned stg = base + (unsigned)(s & 1) * GEMM_STG;
        if (s + 1 < S) {
            load_stage(s + 1, base + (unsigned)((s + 1) & 1) * GEMM_STG);
            cp_wait<1>();
        } else {
            cp_wait<0>();
        }
        __syncthreads();

        const unsigned stgA  = stg;
        const unsigned stgAl = stg + 16384;
        const unsigned stgB  = stg + 32768;
        const unsigned stgBl = stg + 65536;

#pragma unroll
        for (int ks = 0; ks < 4; ks++) {
            unsigned ah[4][4], al[4][4], bb[8][2];
            // A frags: rows = wm*64 + t*16 + (lane&15); chunk = ks*2 + (lane>>4)
            const unsigned akoff = ((unsigned)((ks * 2 + (lane >> 4)) ^ (lane & 7))) << 4;
#pragma unroll
            for (int t = 0; t < 4; t++) {
                const unsigned ro = (unsigned)((wm * 64 + t * 16 + (lane & 15)) * 128);
                LDSM4(ah[t], stgA  + ro + akoff);
                LDSM4(al[t], stgAl + ro + akoff);
            }
            // B frags: rows = wn*64 + p*16 + (lane&7) + ((lane&16)>>1); chunk = ks*2 + ((lane>>3)&1)
            const unsigned bkoff = ((unsigned)((ks * 2 + ((lane >> 3) & 1)) ^ (lane & 7))) << 4;
#pragma unroll
            for (int p = 0; p < 4; p++) {
                const unsigned ro = (unsigned)((wn * 64 + p * 16 + (lane & 7) + ((lane & 16) >> 1)) * 128);
                unsigned r[4];
                LDSM4(r, stgB + ro + bkoff);
                bb[2*p][0] = r[0]; bb[2*p][1] = r[1];
                bb[2*p+1][0] = r[2]; bb[2*p+1][1] = r[3];
            }
            // hi*hi and lo*hi
#pragma unroll
            for (int t = 0; t < 4; t++)
#pragma unroll
                for (int u = 0; u < 8; u++) {
                    MMA16816(acc[t][u], ah[t], bb[u]);
                    MMA16816(acc[t][u], al[t], bb[u]);
                }
            // B lo
#pragma unroll
            for (int p = 0; p < 4; p++) {
                const unsigned ro = (unsigned)((wn * 64 + p * 16 + (lane & 7) + ((lane & 16) >> 1)) * 128);
                unsigned r[4];
                LDSM4(r, stgBl + ro + bkoff);
                bb[2*p][0] = r[0]; bb[2*p][1] = r[1];
                bb[2*p+1][0] = r[2]; bb[2*p+1][1] = r[3];
            }
#pragma unroll
            for (int t = 0; t < 4; t++)
#pragma unroll
                for (int u = 0; u < 8; u++)
                    MMA16816(acc[t][u], ah[t], bb[u]);
        }
        __syncthreads();
    }

    // ---- epilogue: d0,d1 -> (row, col..col+1); d2,d3 -> (row+8, ...)
#pragma unroll
    for (int t = 0; t < 4; t++) {
        const int row = m0 + wm * 64 + t * 16 + (lane >> 2);
#pragma unroll
        for (int u = 0; u < 8; u++) {
            const int col = n0 + wn * 64 + u * 8 + (lane & 3) * 2;
            if (col < N) {
                *(float2*)(C + (size_t)row * N + col)       = make_float2(acc[t][u][0], acc[t][u][1]);
                *(float2*)(C + (size_t)(row + 8) * N + col) = make_float2(acc[t][u][2], acc[t][u][3]);
            }
        }
    }
}

// =====================================================================
// fp32 -> (bf16 hi, bf16 lo) split conversion, float4 granularity
// =====================================================================
__global__ void __launch_bounds__(256) cvt_pair(const float* __restrict__ src,
                                                __nv_bfloat16* __restrict__ h,
                                                __nv_bfloat16* __restrict__ l, int n4)
{
    const int i = blockIdx.x * 256 + threadIdx.x;
    if (i >= n4) return;
    const float4 v = ((const float4*)src)[i];
    __nv_bfloat16 h0 = __float2bfloat16(v.x), h1 = __float2bfloat16(v.y),
                  h2 = __float2bfloat16(v.z), h3 = __float2bfloat16(v.w);
    __nv_bfloat16 l0 = __float2bfloat16(v.x - __bfloat162float(h0));
    __nv_bfloat16 l1 = __float2bfloat16(v.y - __bfloat162float(h1));
    __nv_bfloat16 l2 = __float2bfloat16(v.z - __bfloat162float(h2));
    __nv_bfloat16 l3 = __float2bfloat16(v.w - __bfloat162float(h3));
    ushort4 hv = make_ushort4(*(unsigned short*)&h0, *(unsigned short*)&h1,
                              *(unsigned short*)&h2, *(unsigned short*)&h3);
    ushort4 lv = make_ushort4(*(unsigned short*)&l0, *(unsigned short*)&l1,
                              *(unsigned short*)&l2, *(unsigned short*)&l3);
    ((ushort4*)h)[i] = hv;
    ((ushort4*)l)[i] = lv;
}

// =====================================================================
// Depthwise causal conv (width 4) + SiLU over xBC slice of zxbcdt
// =====================================================================
__global__ void __launch_bounds__(256) conv_silu_kernel(const float* __restrict__ conv_w,
                                                        const float* __restrict__ conv_b)
{
    const int c  = blockIdx.x * 256 + threadIdx.x;
    const int l0 = blockIdx.y * 128;
    const int b  = blockIdx.z;

    const float w0 = conv_w[c*4+0], w1 = conv_w[c*4+1],
                w2 = conv_w[c*4+2], w3 = conv_w[c*4+3];
    const float bias = conv_b[c];

    const float* src = g_zxb + (size_t)(b*SEQ) * D_IN_PROJ + D_INNER + c;
    float*       dst = g_xbc + (size_t)(b*SEQ) * CONV_DIM + c;

    float xm3 = (l0-3 >= 0) ? src[(size_t)(l0-3) * D_IN_PROJ] : 0.f;
    float xm2 = (l0-2 >= 0) ? src[(size_t)(l0-2) * D_IN_PROJ] : 0.f;
    float xm1 = (l0-1 >= 0) ? src[(size_t)(l0-1) * D_IN_PROJ] : 0.f;

    for (int l = l0; l < l0 + 128; l++) {
        const float xc = src[(size_t)l * D_IN_PROJ];
        float v = bias + w0*xm3 + w1*xm2 + w2*xm1 + w3*xc;
        v = v / (1.f + expf(-v));
        dst[(size_t)l * CONV_DIM] = v;
        xm3 = xm2; xm2 = xm1; xm1 = xc;
    }
}

// =====================================================================
// dt = softplus(raw + dt_bias); dA = exp(-exp(A_log)*dt)   layout [b][h][l]
// =====================================================================
__global__ void __launch_bounds__(256) dt_kernel(const float* __restrict__ dt_bias,
                                                 const float* __restrict__ A_log)
{
    const int idx = blockIdx.x * 256 + threadIdx.x;
    if (idx >= BATCH*NHEADS*SEQ) return;
    const int l = idx & (SEQ-1);
    const int h = (idx >> 11) & (NHEADS-1);
    const int b = idx >> 16;
    const float raw = g_zxb[(size_t)(b*SEQ + l) * D_IN_PROJ + (D_IN_PROJ - NHEADS) + h]
                      + dt_bias[h];
    const float sp = (raw > 20.f) ? raw : log1pf(expf(raw));
    const float Ahv = -expf(A_log[h]);
    g_dt[idx] = sp;
    g_dA[idx] = expf(Ahv * sp);
}

// =====================================================================
// Selective scan: one CTA per (b, head). f32x2-packed state, cp.async staging.
// =====================================================================
__global__ void __launch_bounds__(256) scan_kernel(const float* __restrict__ Dvec)
{
    const int bh  = blockIdx.x;
    const int b   = bh >> 5;
    const int hh  = bh & (NHEADS-1);
    const int tid = threadIdx.x;
    const int p   = tid >> 2;
    const int q   = tid & 3;

    __shared__ __align__(16) float sB[2][8][D_STATE];
    __shared__ __align__(16) float sC[2][8][D_STATE];
    __shared__ __align__(16) float sX[2][8][HEADDIM];
    __shared__ float sDt[SEQ];
    __shared__ float sDA[SEQ];

    const float* dtp = g_dt + (size_t)bh * SEQ;
    const float* dap = g_dA + (size_t)bh * SEQ;
    for (int i = tid; i < SEQ; i += 256) { sDt[i] = dtp[i]; sDA[i] = dap[i]; }

    const float Dv = Dvec[hh];

    ull h2[16];
#pragma unroll
    for (int i = 0; i < 16; i++) h2[i] = 0ull;

    auto preload = [&](int blk, int buf) {
        const int t0 = blk * 8;
        {
            const int s = tid >> 5, seg = tid & 31;
            const float* rowp = g_xbc + (size_t)(b*SEQ + t0 + s) * CONV_DIM;
            cp16(smem_u32(&sB[buf][s][seg*4]), rowp + D_INNER + seg*4);
            cp16(smem_u32(&sC[buf][s][seg*4]), rowp + D_INNER + D_STATE + seg*4);
        }
        if (tid < 128) {
            const int s = tid >> 4, seg = tid & 15;
            const float* rowp = g_xbc + (size_t)(b*SEQ + t0 + s) * CONV_DIM;
            cp16(smem_u32(&sX[buf][s][seg*4]), rowp + hh*HEADDIM + seg*4);
        }
        cp_commit();
    };

    const int NBLK = SEQ / 8;
    int buf = 0;
    preload(0, 0);

    for (int blk = 0; blk < NBLK; blk++) {
        if (blk + 1 < NBLK) { preload(blk + 1, buf ^ 1); cp_wait<1>(); }
        else                { cp_wait<0>(); }
        __syncthreads();

#pragma unroll
        for (int s = 0; s < 8; s++) {
            const int t = blk*8 + s;
            const float dtv = sDt[t];
            const float dav = sDA[t];
            const float xv  = sX[buf][s][p];
            const float coef = dtv * xv;
            const ull dA2 = pack2(dav, dav);
            const ull cf2 = pack2(coef, coef);
            const ull* Bp = (const ull*)&sB[buf][s][q*32];
            const ull* Cp = (const ull*)&sC[buf][s][q*32];
            ull yacc = 0ull;
#pragma unroll
            for (int i = 0; i < 16; i++) {
                ull t2 = mul2(cf2, Bp[i]);
                fma2(t2, h2[i], dA2);
                h2[i] = t2;
                fma2(yacc, t2, Cp[i]);
            }
            float ylo, yhi; unpack2(yacc, ylo, yhi);
            float yv = ylo + yhi;
            yv += __shfl_xor_sync(0xffffffffu, yv, 1);
            yv += __shfl_xor_sync(0xffffffffu, yv, 2);
            if (q == 0) {
                g_yb[((size_t)(b*SEQ + t) * NHEADS + hh) * HEADDIM + p] = yv + Dv * xv;
            }
        }
        __syncthreads();
        buf ^= 1;
    }
}

// =====================================================================
// y = yb * silu(z); rmsnorm; write bf16 hi/lo split (GEMM2 A operand)
// =====================================================================
__global__ void __launch_bounds__(256) gate_norm_kernel(const float* __restrict__ norm_w)
{
    const int row = blockIdx.x;
    const int tid = threadIdx.x;
    const float* yb = g_yb + (size_t)row * D_INNER;
    const float* zr = g_zxb + (size_t)row * D_IN_PROJ;

    float v[8];
    float ss = 0.f;
#pragma unroll
    for (int j = 0; j < 8; j++) {
        const int idx = tid + j*256;
        const float z = zr[idx];
        const float sg = z / (1.f + expf(-z));
        const float val = yb[idx] * sg;
        v[j] = val;
        ss += val * val;
    }
#pragma unroll
    for (int o = 16; o > 0; o >>= 1) ss += __shfl_xor_sync(0xffffffffu, ss, o);

    __shared__ float red[8];
    __shared__ float sscale;
    if ((tid & 31) == 0) red[tid >> 5] = ss;
    __syncthreads();
    if (tid == 0) {
        float tot = 0.f;
#pragma unroll
        for (int i = 0; i < 8; i++) tot += red[i];
        sscale = rsqrtf(tot / (float)D_INNER + EPSV);
    }
    __syncthreads();
    const float scale = sscale;

    __nv_bfloat16* oh = g_ynh + (size_t)row * D_INNER;
    __nv_bfloat16* ol = g_ynl + (size_t)row * D_INNER;
#pragma unroll
    for (int j = 0; j < 8; j++) {
        const int idx = tid + j*256;
        const float y = v[j] * scale * norm_w[idx];
        const __nv_bfloat16 hi = __float2bfloat16(y);
        oh[idx] = hi;
        ol[idx] = __float2bfloat16(y - __bfloat162float(hi));
    }
}

// =====================================================================
// Launch
// inputs: 0 query, 1 key, 2 value, 3 in_proj_w, 4 conv_w, 5 conv_b,
//         6 dt_bias, 7 A_log, 8 D, 9 norm_w, 10 out_proj_w
// =====================================================================
extern "C" void kernel_launch(void* const* d_in, const int* in_sizes, int n_in,
                              void* d_out, int out_size)
{
    const float* q          = (const float*)d_in[0];
    const float* in_proj_w  = (const float*)d_in[3];
    const float* conv_w     = (const float*)d_in[4];
    const float* conv_b     = (const float*)d_in[5];
    const float* dt_bias    = (const float*)d_in[6];
    const float* A_log      = (const float*)d_in[7];
    const float* Dvec       = (const float*)d_in[8];
    const float* norm_w     = (const float*)d_in[9];
    const float* out_proj_w = (const float*)d_in[10];
    float* out              = (float*)d_out;

    float* zxb; cudaGetSymbolAddress((void**)&zxb, g_zxb);
    __nv_bfloat16 *qh, *ql, *w1h, *w1l, *ynh, *ynl, *w2h, *w2l;
    cudaGetSymbolAddress((void**)&qh,  g_qh);
    cudaGetSymbolAddress((void**)&ql,  g_ql);
    cudaGetSymbolAddress((void**)&w1h, g_w1h);
    cudaGetSymbolAddress((void**)&w1l, g_w1l);
    cudaGetSymbolAddress((void**)&ynh, g_ynh);
    cudaGetSymbolAddress((void**)&ynl, g_ynl);
    cudaGetSymbolAddress((void**)&w2h, g_w2h);
    cudaGetSymbolAddress((void**)&w2l, g_w2l);

    cudaFuncSetAttribute(gemm_mma, cudaFuncAttributeMaxDynamicSharedMemorySize, GEMM_SMEM);

    // 0) split-convert GEMM operands
    {
        const int nq = ROWS * D_MODEL / 4;
        cvt_pair<<<(nq + 255)/256, 256>>>(q, qh, ql, nq);
        const int nw1 = D_IN_PROJ * D_MODEL / 4;
        cvt_pair<<<(nw1 + 255)/256, 256>>>(in_proj_w, w1h, w1l, nw1);
        const int nw2 = D_MODEL * D_INNER / 4;
        cvt_pair<<<(nw2 + 255)/256, 256>>>(out_proj_w, w2h, w2l, nw2);
    }

    // 1) zxbcdt = q @ in_proj_w^T : [8192,1024] x [4384,1024]^T
    gemm_mma<<<dim3((D_IN_PROJ + 255)/256, ROWS/128), 256, GEMM_SMEM>>>(
        qh, ql, w1h, w1l, zxb, ROWS, D_IN_PROJ, D_MODEL);

    // 2) causal conv4 + SiLU
    conv_silu_kernel<<<dim3(CONV_DIM/256, SEQ/128, BATCH), 256>>>(conv_w, conv_b);

    // 3) dt / dA
    dt_kernel<<<(BATCH*NHEADS*SEQ + 255)/256, 256>>>(dt_bias, A_log);

    // 4) selective scan
    scan_kernel<<<BATCH*NHEADS, 256>>>(Dvec);

    // 5) gate + RMSNorm (emits bf16 hi/lo)
    gate_norm_kernel<<<ROWS, 256>>>(norm_w);

    // 6) out = yn @ out_proj_w^T : [8192,2048] x [1024,2048]^T
    gemm_mma<<<dim3(D_MODEL/256, ROWS/128), 256, GEMM_SMEM>>>(
        ynh, ynl, w2h, w2l, out, ROWS, D_MODEL, D_INNER);
}